// round 1
// baseline (speedup 1.0000x reference)
#include <cuda_runtime.h>
#include <math.h>

#define EC_MAX 64
#define BLK 256

// Per-element packed params: 3 float4 per element:
//  p0 = {cx, cy, cz, |const|}
//  p1 = {c00, c01, c02, c11}
//  p2 = {c12, c22, 0, 0}
__device__ float4 g_prm[EC_MAX * 3];
__device__ float g_pen_accum;   // sum over points of sum_e max(rbf-0.01, 0)
__device__ float g_pen_bbox;    // bbox penalty on centers

__device__ __forceinline__ float sigmoidf_fast(float x) {
    return __fdividef(1.0f, 1.0f + __expf(-x));
}

__global__ void rbf_setup(const float* __restrict__ constants,
                          const float* __restrict__ centers,
                          const float* __restrict__ radii,
                          const float* __restrict__ rotations,
                          int ec) {
    __shared__ float sb[EC_MAX];
    int e = threadIdx.x;
    if (e == 0) g_pen_accum = 0.0f;   // re-zeroed every graph replay
    float bp = 0.0f;
    if (e < ec) {
        float cx0 = centers[3*e+0];
        float cy0 = centers[3*e+1];
        float cz0 = centers[3*e+2];

        // bbox penalty: min = [-0.6,-0.6,-0.35], max = [0.6,0.6,0.6]
        bp += fmaxf(cx0 - 0.6f, 0.0f) + fmaxf(-0.6f  - cx0, 0.0f);
        bp += fmaxf(cy0 - 0.6f, 0.0f) + fmaxf(-0.6f  - cy0, 0.0f);
        bp += fmaxf(cz0 - 0.6f, 0.0f) + fmaxf(-0.35f - cz0, 0.0f);

        float cab = fabsf(constants[e]);
        float d0 = 1.0f / (fabsf(radii[3*e+0]) + 0.005f + 1e-8f);
        float d1 = 1.0f / (fabsf(radii[3*e+1]) + 0.005f + 1e-8f);
        float d2 = 1.0f / (fabsf(radii[3*e+2]) + 0.005f + 1e-8f);

        float sx, cx, sy, cy, sz, cz;
        sincosf(rotations[3*e+0], &sx, &cx);
        sincosf(rotations[3*e+1], &sy, &cy);
        sincosf(rotations[3*e+2], &sz, &cz);

        float R00 = cz * cy;
        float R01 = cz * sy * sx - sz * cx;
        float R02 = cz * sy * cx + sz * sx;
        float R10 = sz * cy;
        float R11 = sz * sy * sx + cz * cx;
        float R12 = sz * sy * cx - cz * sx;
        float R20 = -sy;
        float R21 = cy * sx;
        float R22 = cy * cx;

        // inv_cov = R diag(d) R^T  (symmetric)
        float c00 = R00*R00*d0 + R01*R01*d1 + R02*R02*d2;
        float c01 = R00*R10*d0 + R01*R11*d1 + R02*R12*d2;
        float c02 = R00*R20*d0 + R01*R21*d1 + R02*R22*d2;
        float c11 = R10*R10*d0 + R11*R11*d1 + R12*R12*d2;
        float c12 = R10*R20*d0 + R11*R21*d1 + R12*R22*d2;
        float c22 = R20*R20*d0 + R21*R21*d1 + R22*R22*d2;

        g_prm[e*3 + 0] = make_float4(cx0, cy0, cz0, cab);
        g_prm[e*3 + 1] = make_float4(c00, c01, c02, c11);
        g_prm[e*3 + 2] = make_float4(c12, c22, 0.0f, 0.0f);
    }
    sb[threadIdx.x] = bp;
    __syncthreads();
    if (threadIdx.x == 0) {
        float s = 0.0f;
        for (int i = 0; i < blockDim.x; ++i) s += sb[i];
        g_pen_bbox = s;
    }
}

__global__ void __launch_bounds__(BLK) rbf_main(
    const float* __restrict__ wsp,
    const float4* __restrict__ act,
    const float* __restrict__ dists,
    float4* __restrict__ out,
    int N, int ec)
{
    __shared__ float4 sp[EC_MAX * 3];
    __shared__ float wpen[BLK / 32];

    int tid = threadIdx.x;
    for (int i = tid; i < ec * 3; i += BLK) sp[i] = g_prm[i];
    __syncthreads();

    int n = blockIdx.x * BLK + tid;
    float pen = 0.0f;

    if (n < N) {
        float px = wsp[3*n + 0];
        float py = wsp[3*n + 1];
        float pz = wsp[3*n + 2];
        float dist = dists[n];

        float sum = 0.0f;
        float ax = 0.0f, ay = 0.0f, az = 0.0f, aw = 0.0f;

        #pragma unroll 4
        for (int e = 0; e < ec; ++e) {
            float4 p0 = sp[e*3 + 0];
            float4 p1 = sp[e*3 + 1];
            float4 p2 = sp[e*3 + 2];

            float dx = px - p0.x;
            float dy = py - p0.y;
            float dz = pz - p0.z;

            // q = diff^T * inv_cov * diff
            float tx = fmaf(p1.x, dx, fmaf(p1.y, dy, p1.z * dz));
            float ty = fmaf(p1.y, dx, fmaf(p1.w, dy, p2.x * dz));
            float tz = fmaf(p1.z, dx, fmaf(p2.x, dy, p2.y * dz));
            float q  = fmaf(dx, tx, fmaf(dy, ty, dz * tz));

            float rbf = __expf(-0.5f * q) * p0.w;
            sum += rbf;
            pen += fmaxf(rbf - 0.01f, 0.0f);

            float4 a = __ldg(&act[(size_t)e * N + n]);
            float alpha = 1.0f - __expf(-fmaxf(a.w, 0.0f) * dist);

            ax = fmaf(rbf, sigmoidf_fast(a.x), ax);
            ay = fmaf(rbf, sigmoidf_fast(a.y), ay);
            az = fmaf(rbf, sigmoidf_fast(a.z), az);
            aw = fmaf(rbf, alpha, aw);
        }

        float winv = __fdividef(1.0f, sum + 1e-6f);
        out[n] = make_float4(ax * winv, ay * winv, az * winv, aw * winv);
    }

    // block-level penalty reduction -> one atomic per block
    #pragma unroll
    for (int off = 16; off; off >>= 1)
        pen += __shfl_xor_sync(0xffffffffu, pen, off);
    if ((tid & 31) == 0) wpen[tid >> 5] = pen;
    __syncthreads();
    if (tid == 0) {
        float s = 0.0f;
        #pragma unroll
        for (int w = 0; w < BLK / 32; ++w) s += wpen[w];
        atomicAdd(&g_pen_accum, s);
    }
}

__global__ void rbf_finalize(float* __restrict__ out, int N, int out_size) {
    if (out_size > 4 * N) {
        out[out_size - 1] = 0.001f * g_pen_accum / (float)N + g_pen_bbox;
    }
}

extern "C" void kernel_launch(void* const* d_in, const int* in_sizes, int n_in,
                              void* d_out, int out_size) {
    const float*  wsp       = (const float*)d_in[0];
    const float4* act       = (const float4*)d_in[1];
    const float*  dists     = (const float*)d_in[2];
    const float*  constants = (const float*)d_in[3];
    const float*  centers   = (const float*)d_in[4];
    const float*  radii     = (const float*)d_in[5];
    const float*  rotations = (const float*)d_in[6];

    int N  = in_sizes[0] / 3;
    int ec = in_sizes[3];
    if (ec > EC_MAX) ec = EC_MAX;

    int setup_threads = ((ec + 31) / 32) * 32;
    rbf_setup<<<1, setup_threads>>>(constants, centers, radii, rotations, ec);

    int blocks = (N + BLK - 1) / BLK;
    rbf_main<<<blocks, BLK>>>(wsp, act, dists, (float4*)d_out, N, ec);

    rbf_finalize<<<1, 1>>>((float*)d_out, N, out_size);
}

// round 2
// speedup vs baseline: 1.4029x; 1.4029x over previous
#include <cuda_runtime.h>
#include <math.h>

#define EC_MAX 64
#define BLK 256
#define PTS 2            // points per thread
#define PTS_PER_BLK (BLK * PTS)

// per-block penalty partials (N=262144 -> 512 blocks; sized generously)
__device__ float g_pen_part[8192];

// sigmoid via single HW MUFU tanh: sigma(x) = 0.5*tanh(x/2) + 0.5
__device__ __forceinline__ float fsig(float x) {
    float t;
    asm("tanh.approx.f32 %0, %1;" : "=f"(t) : "f"(x * 0.5f));
    return fmaf(t, 0.5f, 0.5f);
}

// Per-element packed params in smem: 3 float4 per element:
//  p0 = {cx, cy, cz, |const|}
//  p1 = {c00, c01, c02, c11}
//  p2 = {c12, c22, 0, 0}
__device__ __forceinline__ void compute_params(
    float4* sp, int ec,
    const float* __restrict__ constants,
    const float* __restrict__ centers,
    const float* __restrict__ radii,
    const float* __restrict__ rotations)
{
    int e = threadIdx.x;
    if (e < ec) {
        float cx0 = centers[3*e+0];
        float cy0 = centers[3*e+1];
        float cz0 = centers[3*e+2];
        float cab = fabsf(constants[e]);
        float d0 = __fdividef(1.0f, fabsf(radii[3*e+0]) + 0.005f + 1e-8f);
        float d1 = __fdividef(1.0f, fabsf(radii[3*e+1]) + 0.005f + 1e-8f);
        float d2 = __fdividef(1.0f, fabsf(radii[3*e+2]) + 0.005f + 1e-8f);

        float sx, cx, sy, cy, sz, cz;
        __sincosf(rotations[3*e+0], &sx, &cx);
        __sincosf(rotations[3*e+1], &sy, &cy);
        __sincosf(rotations[3*e+2], &sz, &cz);

        float R00 = cz * cy;
        float R01 = cz * sy * sx - sz * cx;
        float R02 = cz * sy * cx + sz * sx;
        float R10 = sz * cy;
        float R11 = sz * sy * sx + cz * cx;
        float R12 = sz * sy * cx - cz * sx;
        float R20 = -sy;
        float R21 = cy * sx;
        float R22 = cy * cx;

        float c00 = R00*R00*d0 + R01*R01*d1 + R02*R02*d2;
        float c01 = R00*R10*d0 + R01*R11*d1 + R02*R12*d2;
        float c02 = R00*R20*d0 + R01*R21*d1 + R02*R22*d2;
        float c11 = R10*R10*d0 + R11*R11*d1 + R12*R12*d2;
        float c12 = R10*R20*d0 + R11*R21*d1 + R12*R22*d2;
        float c22 = R20*R20*d0 + R21*R21*d1 + R22*R22*d2;

        sp[e*3 + 0] = make_float4(cx0, cy0, cz0, cab);
        sp[e*3 + 1] = make_float4(c00, c01, c02, c11);
        sp[e*3 + 2] = make_float4(c12, c22, 0.0f, 0.0f);
    }
}

__global__ void __launch_bounds__(BLK) rbf_main(
    const float* __restrict__ wsp,
    const float4* __restrict__ act,
    const float* __restrict__ dists,
    float4* __restrict__ out,
    const float* __restrict__ constants,
    const float* __restrict__ centers,
    const float* __restrict__ radii,
    const float* __restrict__ rotations,
    int N, int ec)
{
    __shared__ float4 sp[EC_MAX * 3];
    __shared__ float wpen[BLK / 32];

    int tid = threadIdx.x;
    compute_params(sp, ec, constants, centers, radii, rotations);
    __syncthreads();

    int n0 = blockIdx.x * PTS_PER_BLK + tid;
    int n1 = n0 + BLK;
    bool v0 = n0 < N, v1 = n1 < N;

    float px0=0,py0=0,pz0=0,dist0=0, px1=0,py1=0,pz1=0,dist1=0;
    if (v0) { px0 = wsp[3*n0]; py0 = wsp[3*n0+1]; pz0 = wsp[3*n0+2]; dist0 = dists[n0]; }
    if (v1) { px1 = wsp[3*n1]; py1 = wsp[3*n1+1]; pz1 = wsp[3*n1+2]; dist1 = dists[n1]; }

    float sum0=0, ax0=0, ay0=0, az0=0, aw0=0;
    float sum1=0, ax1=0, ay1=0, az1=0, aw1=0;
    float pen = 0.0f;

    #pragma unroll 4
    for (int e = 0; e < ec; ++e) {
        float4 p0 = sp[e*3 + 0];
        float4 p1 = sp[e*3 + 1];
        float4 p2 = sp[e*3 + 2];

        // kick off both streaming loads early (evict-first: data is read once)
        float4 a0 = v0 ? __ldcs(&act[(size_t)e * N + n0]) : make_float4(0,0,0,0);
        float4 a1 = v1 ? __ldcs(&act[(size_t)e * N + n1]) : make_float4(0,0,0,0);

        // point 0
        {
            float dx = px0 - p0.x, dy = py0 - p0.y, dz = pz0 - p0.z;
            float tx = fmaf(p1.x, dx, fmaf(p1.y, dy, p1.z * dz));
            float ty = fmaf(p1.y, dx, fmaf(p1.w, dy, p2.x * dz));
            float tz = fmaf(p1.z, dx, fmaf(p2.x, dy, p2.y * dz));
            float q  = fmaf(dx, tx, fmaf(dy, ty, dz * tz));
            float rbf = __expf(-0.5f * q) * p0.w;
            sum0 += rbf;
            pen  += fmaxf(rbf - 0.01f, 0.0f);
            float alpha = 1.0f - __expf(-fmaxf(a0.w, 0.0f) * dist0);
            ax0 = fmaf(rbf, fsig(a0.x), ax0);
            ay0 = fmaf(rbf, fsig(a0.y), ay0);
            az0 = fmaf(rbf, fsig(a0.z), az0);
            aw0 = fmaf(rbf, alpha, aw0);
        }
        // point 1
        {
            float dx = px1 - p0.x, dy = py1 - p0.y, dz = pz1 - p0.z;
            float tx = fmaf(p1.x, dx, fmaf(p1.y, dy, p1.z * dz));
            float ty = fmaf(p1.y, dx, fmaf(p1.w, dy, p2.x * dz));
            float tz = fmaf(p1.z, dx, fmaf(p2.x, dy, p2.y * dz));
            float q  = fmaf(dx, tx, fmaf(dy, ty, dz * tz));
            float rbf = __expf(-0.5f * q) * p0.w;
            sum1 += rbf;
            pen  += fmaxf(rbf - 0.01f, 0.0f);
            float alpha = 1.0f - __expf(-fmaxf(a1.w, 0.0f) * dist1);
            ax1 = fmaf(rbf, fsig(a1.x), ax1);
            ay1 = fmaf(rbf, fsig(a1.y), ay1);
            az1 = fmaf(rbf, fsig(a1.z), az1);
            aw1 = fmaf(rbf, alpha, aw1);
        }
    }

    if (v0) {
        float winv = __fdividef(1.0f, sum0 + 1e-6f);
        out[n0] = make_float4(ax0 * winv, ay0 * winv, az0 * winv, aw0 * winv);
    }
    if (v1) {
        float winv = __fdividef(1.0f, sum1 + 1e-6f);
        out[n1] = make_float4(ax1 * winv, ay1 * winv, az1 * winv, aw1 * winv);
    }

    // block penalty reduction -> one store per block (no atomics, no pre-zeroing)
    #pragma unroll
    for (int off = 16; off; off >>= 1)
        pen += __shfl_xor_sync(0xffffffffu, pen, off);
    if ((tid & 31) == 0) wpen[tid >> 5] = pen;
    __syncthreads();
    if (tid == 0) {
        float s = 0.0f;
        #pragma unroll
        for (int w = 0; w < BLK / 32; ++w) s += wpen[w];
        g_pen_part[blockIdx.x] = s;
    }
}

__global__ void __launch_bounds__(512) rbf_finalize(
    float* __restrict__ out,
    const float* __restrict__ centers,
    int N, int out_size, int nblocks, int ec)
{
    __shared__ float sb[512 / 32];
    int tid = threadIdx.x;

    float s = 0.0f;
    for (int i = tid; i < nblocks; i += 512) s += g_pen_part[i];

    // bbox penalty on centers folded into lane partials
    if (tid < ec) {
        float cx0 = centers[3*tid+0], cy0 = centers[3*tid+1], cz0 = centers[3*tid+2];
        float bp = fmaxf(cx0 - 0.6f, 0.0f) + fmaxf(-0.6f  - cx0, 0.0f)
                 + fmaxf(cy0 - 0.6f, 0.0f) + fmaxf(-0.6f  - cy0, 0.0f)
                 + fmaxf(cz0 - 0.6f, 0.0f) + fmaxf(-0.35f - cz0, 0.0f);
        s += bp * (float)N * 1000.0f;   // undo the 0.001/N scale applied below
    }

    #pragma unroll
    for (int off = 16; off; off >>= 1)
        s += __shfl_xor_sync(0xffffffffu, s, off);
    if ((tid & 31) == 0) sb[tid >> 5] = s;
    __syncthreads();
    if (tid == 0) {
        float tot = 0.0f;
        #pragma unroll
        for (int w = 0; w < 512 / 32; ++w) tot += sb[w];
        if (out_size > 4 * N)
            out[out_size - 1] = 0.001f * tot / (float)N;
    }
}

extern "C" void kernel_launch(void* const* d_in, const int* in_sizes, int n_in,
                              void* d_out, int out_size) {
    const float*  wsp       = (const float*)d_in[0];
    const float4* act       = (const float4*)d_in[1];
    const float*  dists     = (const float*)d_in[2];
    const float*  constants = (const float*)d_in[3];
    const float*  centers   = (const float*)d_in[4];
    const float*  radii     = (const float*)d_in[5];
    const float*  rotations = (const float*)d_in[6];

    int N  = in_sizes[0] / 3;
    int ec = in_sizes[3];
    if (ec > EC_MAX) ec = EC_MAX;

    int blocks = (N + PTS_PER_BLK - 1) / PTS_PER_BLK;
    rbf_main<<<blocks, BLK>>>(wsp, act, dists, (float4*)d_out,
                              constants, centers, radii, rotations, N, ec);
    rbf_finalize<<<1, 512>>>((float*)d_out, centers, N, out_size, blocks, ec);
}